// round 1
// baseline (speedup 1.0000x reference)
#include <cuda_runtime.h>
#include <math.h>

#define NV 32768
#define NE 524288
#define NH 128
#define NB 128
#define NPG 256
#define KPOST 1664

// ---------------- scratch (static device globals; no allocation) ----------------
__device__ int   g_cnt[NV];
__device__ int   g_off[NV + 1];
__device__ int   g_cur[NV];
__device__ int   g_csr[NE];
__device__ float g_logd[NV];
__device__ float g_amp[NV];
__device__ float g_att[NV];
__device__ float g_avg;
__device__ float g_lossb[NB];
__device__ float g_zero128[NH];
__device__ float g_state[NV * NH];
__device__ float g_tmp[NV * NH];
__device__ float g_Ap[NV * NH];
__device__ float g_Bp[NV * NH];
__device__ float g_h1[NV * NH];
__device__ float g_A1[NV * 2];
__device__ float g_B1[NV * 2];
__device__ float g_feat1[NV * 26];
__device__ float g_feat[(size_t)NV * KPOST];   // [V, 1664] scaled features

// ---------------- setup kernels ----------------
__global__ void k_zero() {
    int i = blockIdx.x * blockDim.x + threadIdx.x;
    if (i < NV) { g_cnt[i] = 0; g_cur[i] = 0; }
    if (i < NB) g_lossb[i] = 0.f;
    if (i < NH) g_zero128[i] = 0.f;
    if (i == 0) g_avg = 0.f;
}

__global__ void k_hist(const int* __restrict__ ei) {
    int e = blockIdx.x * blockDim.x + threadIdx.x;
    if (e < NE) atomicAdd(&g_cnt[ei[NE + e]], 1);
}

__global__ void k_scan() {   // 1 block, 1024 threads, 32 elems each
    __shared__ int sums[1024];
    int t = threadIdx.x;
    int base = t * 32;
    int loc[32];
    int s = 0;
#pragma unroll
    for (int i = 0; i < 32; i++) { loc[i] = s; s += g_cnt[base + i]; }
    sums[t] = s;
    __syncthreads();
    for (int d = 1; d < 1024; d <<= 1) {
        int v = (t >= d) ? sums[t - d] : 0;
        __syncthreads();
        sums[t] += v;
        __syncthreads();
    }
    int excl = sums[t] - s;
#pragma unroll
    for (int i = 0; i < 32; i++) g_off[base + i] = excl + loc[i];
    if (t == 1023) g_off[NV] = excl + s;
}

__global__ void k_scatter(const int* __restrict__ ei) {
    int e = blockIdx.x * blockDim.x + threadIdx.x;
    if (e < NE) {
        int d = ei[NE + e];
        int p = g_off[d] + atomicAdd(&g_cur[d], 1);
        g_csr[p] = ei[e];   // store src
    }
}

__global__ void k_degstat() {
    int v = blockIdx.x * blockDim.x + threadIdx.x;
    int d = g_cnt[v];
    float degc = fmaxf((float)d, 1.f);
    g_logd[v] = logf(degc + 1.f);
    float l = logf((float)d + 1.f);
#pragma unroll
    for (int s = 16; s; s >>= 1) l += __shfl_xor_sync(0xffffffffu, l, s);
    if ((threadIdx.x & 31) == 0) atomicAdd(&g_avg, l);
}

__global__ void k_ampatt() {
    int v = blockIdx.x * blockDim.x + threadIdx.x;
    float avg = g_avg / (float)NV;
    float logd = g_logd[v];
    g_amp[v] = logd / avg;
    g_att[v] = avg / logd;
}

// ---------------- layer 1 (feature dim 2) ----------------
__global__ void k_pre1(const float* __restrict__ x, const float* __restrict__ w,
                       const float* __restrict__ b) {
    int v = blockIdx.x * blockDim.x + threadIdx.x;
    float x0 = x[2 * v], x1 = x[2 * v + 1];
    // w is (4,2) row-major; rows 0-1: dst coeffs, rows 2-3: src coeffs
    g_A1[2 * v + 0] = x0 * w[0] + x1 * w[2] + b[0];
    g_A1[2 * v + 1] = x0 * w[1] + x1 * w[3] + b[1];
    g_B1[2 * v + 0] = x0 * w[4] + x1 * w[6];
    g_B1[2 * v + 1] = x0 * w[5] + x1 * w[7];
}

__global__ void k_agg1(const float* __restrict__ x) {
    int v = blockIdx.x * blockDim.x + threadIdx.x;
    if (v >= NV) return;
    int beg = g_off[v], end = g_off[v + 1];
    float a0 = g_A1[2 * v], a1 = g_A1[2 * v + 1];
    float s0 = 0, s1 = 0, q0 = 0, q1 = 0;
    float mx0 = -3.4e38f, mx1 = -3.4e38f, mn0 = 3.4e38f, mn1 = 3.4e38f;
    for (int e = beg; e < end; e++) {
        int s = g_csr[e];
        float h0 = a0 + g_B1[2 * s];
        float h1 = a1 + g_B1[2 * s + 1];
        s0 += h0; s1 += h1; q0 += h0 * h0; q1 += h1 * h1;
        mx0 = fmaxf(mx0, h0); mx1 = fmaxf(mx1, h1);
        mn0 = fminf(mn0, h0); mn1 = fminf(mn1, h1);
    }
    int d = end - beg;
    float degc = d > 0 ? (float)d : 1.f;
    float m0 = s0 / degc, m1 = s1 / degc;
    float sd0 = sqrtf(fmaxf(q0 / degc - m0 * m0, 0.f) + 1e-5f);
    float sd1 = sqrtf(fmaxf(q1 / degc - m1 * m1, 0.f) + 1e-5f);
    if (d == 0) { mx0 = mx1 = mn0 = mn1 = 0.f; }
    float am = g_amp[v], at = g_att[v];
    float* fr = g_feat1 + v * 26;
    fr[0] = x[2 * v]; fr[1] = x[2 * v + 1];
    fr[2] = m0;  fr[3] = m1;  fr[4] = sd0;  fr[5] = sd1;
    fr[6] = mx0; fr[7] = mx1; fr[8] = mn0;  fr[9] = mn1;
    fr[10] = m0 * am;  fr[11] = m1 * am;  fr[12] = sd0 * am; fr[13] = sd1 * am;
    fr[14] = mx0 * am; fr[15] = mx1 * am; fr[16] = mn0 * am; fr[17] = mn1 * am;
    fr[18] = m0 * at;  fr[19] = m1 * at;  fr[20] = sd0 * at; fr[21] = sd1 * at;
    fr[22] = mx0 * at; fr[23] = mx1 * at; fr[24] = mn0 * at; fr[25] = mn1 * at;
}

__global__ void k_post1(const float* __restrict__ w, const float* __restrict__ b) {
    // feat1 [V,26] @ w [26,128] + b -> g_tmp. block = one node, 128 threads.
    __shared__ float fr[26];
    int v = blockIdx.x;
    int c = threadIdx.x;
    if (c < 26) fr[c] = g_feat1[v * 26 + c];
    __syncthreads();
    float acc = b[c];
#pragma unroll
    for (int k = 0; k < 26; k++) acc += fr[k] * w[k * NH + c];
    g_tmp[v * NH + c] = acc;
}

// ---------------- generic SGEMM: C[M,128] = A[M,K] @ W[K,128] + bias ----------------
__global__ void __launch_bounds__(256) k_sgemm(const float* __restrict__ A,
                                               const float* __restrict__ W,
                                               const float* __restrict__ bias,
                                               float* __restrict__ C,
                                               int K, int act) {
    __shared__ float As[8][132];
    __shared__ float Bs[8][128];
    int t = threadIdx.x;
    int m0 = blockIdx.x * 128;
    int tx = t & 15, ty = t >> 4;
    int arow = t >> 1, aseg = (t & 1) * 4;
    int brow = t >> 5, bcol = (t & 31) * 4;
    const float* Aptr = A + (m0 + arow) * K + aseg;
    float acc[8][8];
#pragma unroll
    for (int i = 0; i < 8; i++)
#pragma unroll
        for (int j = 0; j < 8; j++) acc[i][j] = 0.f;

    for (int k0 = 0; k0 < K; k0 += 8) {
        float4 av = *(const float4*)(Aptr + k0);
        float4 bv = *(const float4*)(W + (k0 + brow) * 128 + bcol);
        As[aseg + 0][arow] = av.x; As[aseg + 1][arow] = av.y;
        As[aseg + 2][arow] = av.z; As[aseg + 3][arow] = av.w;
        *(float4*)&Bs[brow][bcol] = bv;
        __syncthreads();
#pragma unroll
        for (int kk = 0; kk < 8; kk++) {
            float a[8], b[8];
#pragma unroll
            for (int i = 0; i < 8; i++) a[i] = As[kk][ty * 8 + i];
#pragma unroll
            for (int j = 0; j < 8; j++) b[j] = Bs[kk][tx * 8 + j];
#pragma unroll
            for (int i = 0; i < 8; i++)
#pragma unroll
                for (int j = 0; j < 8; j++) acc[i][j] += a[i] * b[j];
        }
        __syncthreads();
    }
#pragma unroll
    for (int i = 0; i < 8; i++) {
        int row = m0 + ty * 8 + i;
#pragma unroll
        for (int j = 0; j < 8; j++) {
            int col = tx * 8 + j;
            float v = acc[i][j] + bias[col];
            if (act && v < 0.f) v *= 0.01f;
            C[row * 128 + col] = v;
        }
    }
}

// ---------------- aggregation (F=128): block = one node, 128 threads ----------------
__global__ void __launch_bounds__(128) k_agg() {
    __shared__ int s_src[128];
    int v = blockIdx.x;
    int f = threadIdx.x;
    int beg = g_off[v], end = g_off[v + 1];
    float a = g_Ap[v * NH + f];
    float sum = 0.f, sq = 0.f, mx = -3.4e38f, mn = 3.4e38f;
    for (int base = beg; base < end; base += 128) {
        int n = min(128, end - base);
        if (f < n) s_src[f] = g_csr[base + f];
        __syncthreads();
        int e = 0;
        for (; e + 4 <= n; e += 4) {
            int i0 = s_src[e], i1 = s_src[e + 1], i2 = s_src[e + 2], i3 = s_src[e + 3];
            float h0 = a + g_Bp[i0 * NH + f];
            float h1 = a + g_Bp[i1 * NH + f];
            float h2 = a + g_Bp[i2 * NH + f];
            float h3 = a + g_Bp[i3 * NH + f];
            sum += h0 + h1 + h2 + h3;
            sq += h0 * h0 + h1 * h1 + h2 * h2 + h3 * h3;
            mx = fmaxf(mx, fmaxf(fmaxf(h0, h1), fmaxf(h2, h3)));
            mn = fminf(mn, fminf(fminf(h0, h1), fminf(h2, h3)));
        }
        for (; e < n; e++) {
            float h = a + g_Bp[s_src[e] * NH + f];
            sum += h; sq += h * h; mx = fmaxf(mx, h); mn = fminf(mn, h);
        }
        __syncthreads();
    }
    int d = end - beg;
    float degc = d > 0 ? (float)d : 1.f;
    float mean = sum / degc;
    float stdv = sqrtf(fmaxf(sq / degc - mean * mean, 0.f) + 1e-5f);
    if (d == 0) { mx = 0.f; mn = 0.f; }
    float am = g_amp[v], at = g_att[v];
    float* fr = g_feat + (size_t)v * KPOST;
    fr[f] = g_state[v * NH + f];
    fr[128 + f] = mean;       fr[256 + f] = stdv;
    fr[384 + f] = mx;         fr[512 + f] = mn;
    fr[640 + f] = mean * am;  fr[768 + f] = stdv * am;
    fr[896 + f] = mx * am;    fr[1024 + f] = mn * am;
    fr[1152 + f] = mean * at; fr[1280 + f] = stdv * at;
    fr[1408 + f] = mx * at;   fr[1536 + f] = mn * at;
}

// ---------------- readout tail: h2 = leaky(h1@r2+b2); out = leaky(h2@r3+b3) ----------------
__global__ void __launch_bounds__(256) k_readout(const float* __restrict__ r2w,
                                                 const float* __restrict__ r2b,
                                                 const float* __restrict__ r3w,
                                                 const float* __restrict__ r3b,
                                                 const float* __restrict__ tgt,
                                                 float* __restrict__ out) {
    __shared__ float w2[128 * 8];
    int t = threadIdx.x;
    for (int i = t; i < 128 * 8; i += 256) w2[i] = r2w[i];
    __syncthreads();
    int warp = t >> 5, lane = t & 31;
    int v = blockIdx.x * 8 + warp;
    const float* h1 = g_h1 + v * NH;
    float p[8] = {0, 0, 0, 0, 0, 0, 0, 0};
    for (int k = lane; k < 128; k += 32) {
        float hv = h1[k];
#pragma unroll
        for (int j = 0; j < 8; j++) p[j] += hv * w2[k * 8 + j];
    }
#pragma unroll
    for (int j = 0; j < 8; j++)
#pragma unroll
        for (int s = 16; s; s >>= 1) p[j] += __shfl_xor_sync(0xffffffffu, p[j], s);
    if (lane == 0) {
        float h2[8];
#pragma unroll
        for (int j = 0; j < 8; j++) {
            float x = p[j] + r2b[j];
            h2[j] = x < 0.f ? 0.01f * x : x;
        }
        float err = 0.f;
#pragma unroll
        for (int c = 0; c < 3; c++) {
            float o = r3b[c];
#pragma unroll
            for (int j = 0; j < 8; j++) o += h2[j] * r3w[j * 3 + c];
            if (o < 0.f) o *= 0.01f;
            out[v * 3 + c] = o;
            float dd = o - tgt[v * 3 + c];
            err += dd * dd;
        }
        atomicAdd(&g_lossb[v >> 8], err);
    }
}

__global__ void k_loss(float* __restrict__ out) {   // 1 block, 128 threads
    __shared__ float s[128];
    int b = threadIdx.x;
    float l = g_lossb[b] / (float)(NPG * 3);
    out[NV * 3 + 1 + b] = l;
    s[b] = l;
    __syncthreads();
    for (int d = 64; d; d >>= 1) {
        if (b < d) s[b] += s[b + d];
        __syncthreads();
    }
    if (b == 0) out[NV * 3] = s[0] / (float)NB;
}

// ---------------- host ----------------
template <typename T>
static float* sym(T& s) { void* p = nullptr; cudaGetSymbolAddress(&p, s); return (float*)p; }

extern "C" void kernel_launch(void* const* d_in, const int* in_sizes, int n_in,
                              void* d_out, int out_size) {
    const float* x       = (const float*)d_in[0];
    const int*   ei      = (const int*)d_in[1];
    const float* tgt_n   = (const float*)d_in[2];
    const float* pre1_w  = (const float*)d_in[4];
    const float* pre1_b  = (const float*)d_in[5];
    const float* post1_w = (const float*)d_in[6];
    const float* post1_b = (const float*)d_in[7];
    const float* lin1_w  = (const float*)d_in[8];
    const float* lin1_b  = (const float*)d_in[9];
    const float* pre_w   = (const float*)d_in[10];
    const float* pre_b   = (const float*)d_in[11];
    const float* post_w  = (const float*)d_in[12];
    const float* post_b  = (const float*)d_in[13];
    const float* lin_w   = (const float*)d_in[14];
    const float* lin_b   = (const float*)d_in[15];
    const float* r1_w    = (const float*)d_in[16];
    const float* r1_b    = (const float*)d_in[17];
    const float* r2_w    = (const float*)d_in[18];
    const float* r2_b    = (const float*)d_in[19];
    const float* r3_w    = (const float*)d_in[20];
    const float* r3_b    = (const float*)d_in[21];
    float* out = (float*)d_out;

    float* p_state = sym(g_state);
    float* p_tmp   = sym(g_tmp);
    float* p_Ap    = sym(g_Ap);
    float* p_Bp    = sym(g_Bp);
    float* p_h1    = sym(g_h1);
    float* p_feat  = sym(g_feat);
    float* p_zero  = sym(g_zero128);

    // graph setup: degree, CSR, PNA degree scalers
    k_zero<<<NV / 256, 256>>>();
    k_hist<<<NE / 256, 256>>>(ei);
    k_scan<<<1, 1024>>>();
    k_scatter<<<NE / 256, 256>>>(ei);
    k_degstat<<<NV / 256, 256>>>();
    k_ampatt<<<NV / 256, 256>>>();

    // layer 1 (2 -> 128)
    k_pre1<<<NV / 256, 256>>>(x, pre1_w, pre1_b);
    k_agg1<<<NV / 256, 256>>>(x);
    k_post1<<<NV, 128>>>(post1_w, post1_b);                       // -> g_tmp
    k_sgemm<<<NV / 128, 256>>>(p_tmp, lin1_w, lin1_b, p_state, NH, 0);

    // 3 propagation layers (128 -> 128)
    for (int p = 0; p < 3; p++) {
        k_sgemm<<<NV / 128, 256>>>(p_state, pre_w, pre_b, p_Ap, NH, 0);          // dst proj (+bias)
        k_sgemm<<<NV / 128, 256>>>(p_state, pre_w + 128 * 128, p_zero, p_Bp, NH, 0); // src proj
        k_agg<<<NV, 128>>>();                                                     // -> g_feat [V,1664]
        k_sgemm<<<NV / 128, 256>>>(p_feat, post_w, post_b, p_tmp, KPOST, 0);
        k_sgemm<<<NV / 128, 256>>>(p_tmp, lin_w, lin_b, p_state, NH, 0);
    }

    // readout
    k_sgemm<<<NV / 128, 256>>>(p_state, r1_w, r1_b, p_h1, NH, 1);  // leaky
    k_readout<<<NV / 8, 256>>>(r2_w, r2_b, r3_w, r3_b, tgt_n, out);
    k_loss<<<1, 128>>>(out);

    (void)in_sizes; (void)n_in; (void)out_size;
}

// round 3
// speedup vs baseline: 1.6305x; 1.6305x over previous
#include <cuda_runtime.h>
#include <cuda_bf16.h>
#include <math.h>
#include <stdint.h>

#define NV 32768
#define NE 524288
#define NH 128
#define NB 128
#define NPG 256
#define KPOST 1664

// ---------------- warp MMA helpers (family-portable: compute_80+) ----------------
__device__ __forceinline__ uint32_t smem_u32(const void* p) {
    uint32_t a;
    asm("{ .reg .u64 t; cvta.to.shared.u64 t, %1; cvt.u32.u64 %0, t; }" : "=r"(a) : "l"(p));
    return a;
}

#define LDM_X4(r0, r1, r2, r3, addr)                                         \
    asm volatile("ldmatrix.sync.aligned.m8n8.x4.shared.b16 {%0,%1,%2,%3}, [%4];" \
        : "=r"(r0), "=r"(r1), "=r"(r2), "=r"(r3) : "r"(addr))

#define MMA16816(d, a, b0, b1)                                               \
    asm volatile("mma.sync.aligned.m16n8k16.row.col.f32.bf16.bf16.f32 "      \
        "{%0,%1,%2,%3}, {%4,%5,%6,%7}, {%8,%9}, {%0,%1,%2,%3};"              \
        : "+f"((d)[0]), "+f"((d)[1]), "+f"((d)[2]), "+f"((d)[3])             \
        : "r"((a)[0]), "r"((a)[1]), "r"((a)[2]), "r"((a)[3]),                \
          "r"(b0), "r"(b1))

#define STS128(a, r0, r1, r2, r3)                                            \
    asm volatile("st.shared.v4.b32 [%0], {%1, %2, %3, %4};"                  \
        :: "r"(a), "r"(r0), "r"(r1), "r"(r2), "r"(r3) : "memory")

// split one fp32 pair into (hi bf16x2, lo bf16x2)
__device__ __forceinline__ void cvt2(float a, float b, uint32_t& hi, uint32_t& lo) {
    __nv_bfloat16 ha = __float2bfloat16_rn(a), hb = __float2bfloat16_rn(b);
    float ra = a - __bfloat162float(ha);
    float rb = b - __bfloat162float(hb);
    __nv_bfloat16 la = __float2bfloat16_rn(ra), lb = __float2bfloat16_rn(rb);
    unsigned short uha = *(unsigned short*)&ha, uhb = *(unsigned short*)&hb;
    unsigned short ula = *(unsigned short*)&la, ulb = *(unsigned short*)&lb;
    hi = ((uint32_t)uhb << 16) | uha;
    lo = ((uint32_t)ulb << 16) | ula;
}

// ---------------- scratch ----------------
__device__ int   g_cnt[NV];
__device__ int   g_off[NV + 1];
__device__ int   g_cur[NV];
__device__ int   g_csr[NE];
__device__ float g_logd[NV];
__device__ float g_amp[NV];
__device__ float g_att[NV];
__device__ float g_avg;
__device__ float g_lossb[NB];
__device__ float g_zero128[NH];
__device__ float g_state[NV * NH];
__device__ float g_tmp[NV * NH];
__device__ float g_Ap[NV * NH];
__device__ float g_Bp[NV * NH];
__device__ float g_h1[NV * NH];
__device__ float g_A1[NV * 2];
__device__ float g_B1[NV * 2];
__device__ float g_feat1[NV * 26];
__device__ float g_feat[(size_t)NV * KPOST];
// transposed weights (K-major: Wt[n*K + k] = W[k*N + n])
__device__ float g_WtPost[NH * KPOST];
__device__ float g_WtPreA[NH * NH];
__device__ float g_WtPreB[NH * NH];
__device__ float g_WtLin[NH * NH];
__device__ float g_WtLin1[NH * NH];
__device__ float g_WtR1[NH * NH];

// ---------------- setup kernels ----------------
__global__ void k_zero() {
    int i = blockIdx.x * blockDim.x + threadIdx.x;
    if (i < NV) { g_cnt[i] = 0; g_cur[i] = 0; }
    if (i < NB) g_lossb[i] = 0.f;
    if (i < NH) g_zero128[i] = 0.f;
    if (i == 0) g_avg = 0.f;
}

__global__ void k_hist(const int* __restrict__ ei) {
    int e = blockIdx.x * blockDim.x + threadIdx.x;
    if (e < NE) atomicAdd(&g_cnt[ei[NE + e]], 1);
}

__global__ void k_scan() {
    __shared__ int sums[1024];
    int t = threadIdx.x;
    int base = t * 32;
    int loc[32];
    int s = 0;
#pragma unroll
    for (int i = 0; i < 32; i++) { loc[i] = s; s += g_cnt[base + i]; }
    sums[t] = s;
    __syncthreads();
    for (int d = 1; d < 1024; d <<= 1) {
        int v = (t >= d) ? sums[t - d] : 0;
        __syncthreads();
        sums[t] += v;
        __syncthreads();
    }
    int excl = sums[t] - s;
#pragma unroll
    for (int i = 0; i < 32; i++) g_off[base + i] = excl + loc[i];
    if (t == 1023) g_off[NV] = excl + s;
}

__global__ void k_scatter(const int* __restrict__ ei) {
    int e = blockIdx.x * blockDim.x + threadIdx.x;
    if (e < NE) {
        int d = ei[NE + e];
        int p = g_off[d] + atomicAdd(&g_cur[d], 1);
        g_csr[p] = ei[e];
    }
}

__global__ void k_degstat() {
    int v = blockIdx.x * blockDim.x + threadIdx.x;
    int d = g_cnt[v];
    float degc = fmaxf((float)d, 1.f);
    g_logd[v] = logf(degc + 1.f);
    float l = logf((float)d + 1.f);
#pragma unroll
    for (int s = 16; s; s >>= 1) l += __shfl_xor_sync(0xffffffffu, l, s);
    if ((threadIdx.x & 31) == 0) atomicAdd(&g_avg, l);
}

__global__ void k_ampatt() {
    int v = blockIdx.x * blockDim.x + threadIdx.x;
    float avg = g_avg / (float)NV;
    float logd = g_logd[v];
    g_amp[v] = logd / avg;
    g_att[v] = avg / logd;
}

// ---------------- weight transpose: Wt[n*K+k] = W[k*128+n] ----------------
__global__ void k_transpose(const float* __restrict__ W, float* __restrict__ Wt, int K) {
    __shared__ float tile[32][33];
    int kb = blockIdx.x * 32, nb = blockIdx.y * 32;
    int tx = threadIdx.x, ty = threadIdx.y;
    for (int i = ty; i < 32; i += 8)
        tile[i][tx] = W[(kb + i) * NH + nb + tx];
    __syncthreads();
    for (int i = ty; i < 32; i += 8)
        Wt[(nb + i) * K + kb + tx] = tile[tx][i];
}

// ---------------- layer 1 (feature dim 2) ----------------
__global__ void k_pre1(const float* __restrict__ x, const float* __restrict__ w,
                       const float* __restrict__ b) {
    int v = blockIdx.x * blockDim.x + threadIdx.x;
    float x0 = x[2 * v], x1 = x[2 * v + 1];
    g_A1[2 * v + 0] = x0 * w[0] + x1 * w[2] + b[0];
    g_A1[2 * v + 1] = x0 * w[1] + x1 * w[3] + b[1];
    g_B1[2 * v + 0] = x0 * w[4] + x1 * w[6];
    g_B1[2 * v + 1] = x0 * w[5] + x1 * w[7];
}

__global__ void k_agg1(const float* __restrict__ x) {
    int v = blockIdx.x * blockDim.x + threadIdx.x;
    if (v >= NV) return;
    int beg = g_off[v], end = g_off[v + 1];
    float a0 = g_A1[2 * v], a1 = g_A1[2 * v + 1];
    float s0 = 0, s1 = 0, q0 = 0, q1 = 0;
    float mx0 = -3.4e38f, mx1 = -3.4e38f, mn0 = 3.4e38f, mn1 = 3.4e38f;
    for (int e = beg; e < end; e++) {
        int s = g_csr[e];
        float h0 = a0 + g_B1[2 * s];
        float h1 = a1 + g_B1[2 * s + 1];
        s0 += h0; s1 += h1; q0 += h0 * h0; q1 += h1 * h1;
        mx0 = fmaxf(mx0, h0); mx1 = fmaxf(mx1, h1);
        mn0 = fminf(mn0, h0); mn1 = fminf(mn1, h1);
    }
    int d = end - beg;
    float degc = d > 0 ? (float)d : 1.f;
    float m0 = s0 / degc, m1 = s1 / degc;
    float sd0 = sqrtf(fmaxf(q0 / degc - m0 * m0, 0.f) + 1e-5f);
    float sd1 = sqrtf(fmaxf(q1 / degc - m1 * m1, 0.f) + 1e-5f);
    if (d == 0) { mx0 = mx1 = mn0 = mn1 = 0.f; }
    float am = g_amp[v], at = g_att[v];
    float* fr = g_feat1 + v * 26;
    fr[0] = x[2 * v]; fr[1] = x[2 * v + 1];
    fr[2] = m0;  fr[3] = m1;  fr[4] = sd0;  fr[5] = sd1;
    fr[6] = mx0; fr[7] = mx1; fr[8] = mn0;  fr[9] = mn1;
    fr[10] = m0 * am;  fr[11] = m1 * am;  fr[12] = sd0 * am; fr[13] = sd1 * am;
    fr[14] = mx0 * am; fr[15] = mx1 * am; fr[16] = mn0 * am; fr[17] = mn1 * am;
    fr[18] = m0 * at;  fr[19] = m1 * at;  fr[20] = sd0 * at; fr[21] = sd1 * at;
    fr[22] = mx0 * at; fr[23] = mx1 * at; fr[24] = mn0 * at; fr[25] = mn1 * at;
}

__global__ void k_post1(const float* __restrict__ w, const float* __restrict__ b) {
    __shared__ float fr[26];
    int v = blockIdx.x;
    int c = threadIdx.x;
    if (c < 26) fr[c] = g_feat1[v * 26 + c];
    __syncthreads();
    float acc = b[c];
#pragma unroll
    for (int k = 0; k < 26; k++) acc += fr[k] * w[k * NH + c];
    g_tmp[v * NH + c] = acc;
}

// ---------------- HMMA GEMM: C[M,128] = A[M,K] @ Wt^T + bias ----------------
// Wt is [128, K] fp32 K-major. bf16 split: A = Ah+Al, B = Bh+Bl;
// D += Ah*Bh + Ah*Bl + Al*Bh. K multiple of 64. grid = M/128, block = 256.
// smem tiles: halves, row stride 72 (padded). Epilogue staged for coalescing.
#define SROW 72
#define TILE_HALVES (128 * SROW)               // per tile
#define HG_SMEM (4 * TILE_HALVES * 2)          // 73728 bytes (also covers stage 67584)
__global__ void __launch_bounds__(256) k_hgemm(const float* __restrict__ A,
                                               const float* __restrict__ Bt,
                                               const float* __restrict__ bias,
                                               float* __restrict__ C,
                                               int K, int act) {
    extern __shared__ char dsm[];
    uint32_t base = smem_u32(dsm);
    uint32_t sAh = base;
    uint32_t sAl = base + TILE_HALVES * 2;
    uint32_t sBh = base + TILE_HALVES * 4;
    uint32_t sBl = base + TILE_HALVES * 6;

    int t = threadIdx.x;
    int w = t >> 5, lane = t & 31;
    int m0 = blockIdx.x * 128;

    float acc[8][2][4];
#pragma unroll
    for (int g = 0; g < 8; g++)
#pragma unroll
        for (int h = 0; h < 2; h++)
#pragma unroll
            for (int i = 0; i < 4; i++) acc[g][h][i] = 0.f;

    int lrow = t >> 1;               // 0..127
    int lseg = (t & 1) * 32;         // 0 or 32
    const float* arow = A + (size_t)(m0 + lrow) * K + lseg;
    const float* brow = Bt + (size_t)lrow * K + lseg;
    uint32_t aoffA = (uint32_t)(lrow * SROW + lseg) * 2;  // byte offset of this thread's store base

    // ldmatrix source addresses (byte offsets into tiles), per warp/lane
    int frow = lane & 15;            // row within 16-row block
    int fcol = (lane >> 4) * 8;      // 0 or 8 (k offset)
    uint32_t a_ld = (uint32_t)((w * 16 + frow) * SROW + fcol) * 2;
    uint32_t b_ld = (uint32_t)(frow * SROW + fcol) * 2;   // + g*16 rows added in loop

    int nchunks = K >> 6;
    for (int ch = 0; ch < nchunks; ch++) {
        int k0 = ch << 6;
        // ---- load + split A chunk (128 x 64) and B chunk (128 x 64) ----
#pragma unroll
        for (int g = 0; g < 4; g++) {
            float4 v0 = *(const float4*)(arow + k0 + g * 8);
            float4 v1 = *(const float4*)(arow + k0 + g * 8 + 4);
            uint32_t h0, h1, h2, h3, l0, l1, l2, l3;
            cvt2(v0.x, v0.y, h0, l0); cvt2(v0.z, v0.w, h1, l1);
            cvt2(v1.x, v1.y, h2, l2); cvt2(v1.z, v1.w, h3, l3);
            uint32_t off = aoffA + g * 16;
            STS128(sAh + off, h0, h1, h2, h3);
            STS128(sAl + off, l0, l1, l2, l3);
        }
#pragma unroll
        for (int g = 0; g < 4; g++) {
            float4 v0 = *(const float4*)(brow + k0 + g * 8);
            float4 v1 = *(const float4*)(brow + k0 + g * 8 + 4);
            uint32_t h0, h1, h2, h3, l0, l1, l2, l3;
            cvt2(v0.x, v0.y, h0, l0); cvt2(v0.z, v0.w, h1, l1);
            cvt2(v1.x, v1.y, h2, l2); cvt2(v1.z, v1.w, h3, l3);
            uint32_t off = aoffA + g * 16;
            STS128(sBh + off, h0, h1, h2, h3);
            STS128(sBl + off, l0, l1, l2, l3);
        }
        __syncthreads();

        // ---- compute: 4 k16 steps ----
#pragma unroll
        for (int kk = 0; kk < 4; kk++) {
            uint32_t koff = kk * 32;  // 16 halves = 32 bytes
            uint32_t ah[4], al[4];
            LDM_X4(ah[0], ah[1], ah[2], ah[3], sAh + a_ld + koff);
            LDM_X4(al[0], al[1], al[2], al[3], sAl + a_ld + koff);
#pragma unroll
            for (int g = 0; g < 8; g++) {
                uint32_t goff = (uint32_t)(g * 16 * SROW) * 2;
                uint32_t bh0, bh1, bh2, bh3, bl0, bl1, bl2, bl3;
                LDM_X4(bh0, bh1, bh2, bh3, sBh + b_ld + goff + koff);
                LDM_X4(bl0, bl1, bl2, bl3, sBl + b_ld + goff + koff);
                MMA16816(acc[g][0], ah, bh0, bh2);
                MMA16816(acc[g][0], ah, bl0, bl2);
                MMA16816(acc[g][0], al, bh0, bh2);
                MMA16816(acc[g][1], ah, bh1, bh3);
                MMA16816(acc[g][1], ah, bl1, bl3);
                MMA16816(acc[g][1], al, bh1, bh3);
            }
        }
        __syncthreads();
    }

    // ---- epilogue: fragments -> smem stage -> coalesced out ----
    float* stage = (float*)dsm;   // reuse tiles (row stride 132 floats)
    int r0 = w * 16 + (lane >> 2);
    int cbase = (lane & 3) * 2;
#pragma unroll
    for (int g = 0; g < 8; g++)
#pragma unroll
        for (int h = 0; h < 2; h++) {
            int col = g * 16 + h * 8 + cbase;
            float* s0 = stage + r0 * 132 + col;
            s0[0] = acc[g][h][0]; s0[1] = acc[g][h][1];
            float* s1 = stage + (r0 + 8) * 132 + col;
            s1[0] = acc[g][h][2]; s1[1] = acc[g][h][3];
        }
    __syncthreads();
#pragma unroll
    for (int i = 0; i < 16; i++) {
        int idx = t + i * 256;            // 0..4095 float4s
        int row = idx >> 5;
        int c4 = (idx & 31) * 4;
        float4 v = *(const float4*)(stage + row * 132 + c4);
        v.x += __ldg(&bias[c4 + 0]); v.y += __ldg(&bias[c4 + 1]);
        v.z += __ldg(&bias[c4 + 2]); v.w += __ldg(&bias[c4 + 3]);
        if (act) {
            if (v.x < 0.f) v.x *= 0.01f;
            if (v.y < 0.f) v.y *= 0.01f;
            if (v.z < 0.f) v.z *= 0.01f;
            if (v.w < 0.f) v.w *= 0.01f;
        }
        *(float4*)(C + (size_t)(m0 + row) * 128 + c4) = v;
    }
}

// ---------------- aggregation (F=128): block = one node, 128 threads ----------------
__global__ void __launch_bounds__(128) k_agg() {
    __shared__ int s_src[128];
    int v = blockIdx.x;
    int f = threadIdx.x;
    int beg = g_off[v], end = g_off[v + 1];
    float a = g_Ap[v * NH + f];
    float sum = 0.f, sq = 0.f, mx = -3.4e38f, mn = 3.4e38f;
    for (int base = beg; base < end; base += 128) {
        int n = min(128, end - base);
        if (f < n) s_src[f] = g_csr[base + f];
        __syncthreads();
        int e = 0;
        for (; e + 4 <= n; e += 4) {
            int i0 = s_src[e], i1 = s_src[e + 1], i2 = s_src[e + 2], i3 = s_src[e + 3];
            float h0 = a + g_Bp[i0 * NH + f];
            float h1 = a + g_Bp[i1 * NH + f];
            float h2 = a + g_Bp[i2 * NH + f];
            float h3 = a + g_Bp[i3 * NH + f];
            sum += h0 + h1 + h2 + h3;
            sq += h0 * h0 + h1 * h1 + h2 * h2 + h3 * h3;
            mx = fmaxf(mx, fmaxf(fmaxf(h0, h1), fmaxf(h2, h3)));
            mn = fminf(mn, fminf(fminf(h0, h1), fminf(h2, h3)));
        }
        for (; e < n; e++) {
            float h = a + g_Bp[s_src[e] * NH + f];
            sum += h; sq += h * h; mx = fmaxf(mx, h); mn = fminf(mn, h);
        }
        __syncthreads();
    }
    int d = end - beg;
    float degc = d > 0 ? (float)d : 1.f;
    float mean = sum / degc;
    float stdv = sqrtf(fmaxf(sq / degc - mean * mean, 0.f) + 1e-5f);
    if (d == 0) { mx = 0.f; mn = 0.f; }
    float am = g_amp[v], at = g_att[v];
    float* fr = g_feat + (size_t)v * KPOST;
    fr[f] = g_state[v * NH + f];
    fr[128 + f] = mean;       fr[256 + f] = stdv;
    fr[384 + f] = mx;         fr[512 + f] = mn;
    fr[640 + f] = mean * am;  fr[768 + f] = stdv * am;
    fr[896 + f] = mx * am;    fr[1024 + f] = mn * am;
    fr[1152 + f] = mean * at; fr[1280 + f] = stdv * at;
    fr[1408 + f] = mx * at;   fr[1536 + f] = mn * at;
}

// ---------------- readout tail ----------------
__global__ void __launch_bounds__(256) k_readout(const float* __restrict__ r2w,
                                                 const float* __restrict__ r2b,
                                                 const float* __restrict__ r3w,
                                                 const float* __restrict__ r3b,
                                                 const float* __restrict__ tgt,
                                                 float* __restrict__ out) {
    __shared__ float w2[128 * 8];
    int t = threadIdx.x;
    for (int i = t; i < 128 * 8; i += 256) w2[i] = r2w[i];
    __syncthreads();
    int warp = t >> 5, lane = t & 31;
    int v = blockIdx.x * 8 + warp;
    const float* h1 = g_h1 + v * NH;
    float p[8] = {0, 0, 0, 0, 0, 0, 0, 0};
    for (int k = lane; k < 128; k += 32) {
        float hv = h1[k];
#pragma unroll
        for (int j = 0; j < 8; j++) p[j] += hv * w2[k * 8 + j];
    }
#pragma unroll
    for (int j = 0; j < 8; j++)
#pragma unroll
        for (int s = 16; s; s >>= 1) p[j] += __shfl_xor_sync(0xffffffffu, p[j], s);
    if (lane == 0) {
        float h2[8];
#pragma unroll
        for (int j = 0; j < 8; j++) {
            float x = p[j] + r2b[j];
            h2[j] = x < 0.f ? 0.01f * x : x;
        }
        float err = 0.f;
#pragma unroll
        for (int c = 0; c < 3; c++) {
            float o = r3b[c];
#pragma unroll
            for (int j = 0; j < 8; j++) o += h2[j] * r3w[j * 3 + c];
            if (o < 0.f) o *= 0.01f;
            out[v * 3 + c] = o;
            float dd = o - tgt[v * 3 + c];
            err += dd * dd;
        }
        atomicAdd(&g_lossb[v >> 8], err);
    }
}

__global__ void k_loss(float* __restrict__ out) {
    __shared__ float s[128];
    int b = threadIdx.x;
    float l = g_lossb[b] / (float)(NPG * 3);
    out[NV * 3 + 1 + b] = l;
    s[b] = l;
    __syncthreads();
    for (int d = 64; d; d >>= 1) {
        if (b < d) s[b] += s[b + d];
        __syncthreads();
    }
    if (b == 0) out[NV * 3] = s[0] / (float)NB;
}

// ---------------- host ----------------
template <typename T>
static float* sym(T& s) { void* p = nullptr; cudaGetSymbolAddress(&p, s); return (float*)p; }

extern "C" void kernel_launch(void* const* d_in, const int* in_sizes, int n_in,
                              void* d_out, int out_size) {
    const float* x       = (const float*)d_in[0];
    const int*   ei      = (const int*)d_in[1];
    const float* tgt_n   = (const float*)d_in[2];
    const float* pre1_w  = (const float*)d_in[4];
    const float* pre1_b  = (const float*)d_in[5];
    const float* post1_w = (const float*)d_in[6];
    const float* post1_b = (const float*)d_in[7];
    const float* lin1_w  = (const float*)d_in[8];
    const float* lin1_b  = (const float*)d_in[9];
    const float* pre_w   = (const float*)d_in[10];
    const float* pre_b   = (const float*)d_in[11];
    const float* post_w  = (const float*)d_in[12];
    const float* post_b  = (const float*)d_in[13];
    const float* lin_w   = (const float*)d_in[14];
    const float* lin_b   = (const float*)d_in[15];
    const float* r1_w    = (const float*)d_in[16];
    const float* r1_b    = (const float*)d_in[17];
    const float* r2_w    = (const float*)d_in[18];
    const float* r2_b    = (const float*)d_in[19];
    const float* r3_w    = (const float*)d_in[20];
    const float* r3_b    = (const float*)d_in[21];
    float* out = (float*)d_out;

    float* p_state = sym(g_state);
    float* p_tmp   = sym(g_tmp);
    float* p_Ap    = sym(g_Ap);
    float* p_Bp    = sym(g_Bp);
    float* p_h1    = sym(g_h1);
    float* p_feat  = sym(g_feat);
    float* p_zero  = sym(g_zero128);
    float* p_WtPost = sym(g_WtPost);
    float* p_WtPreA = sym(g_WtPreA);
    float* p_WtPreB = sym(g_WtPreB);
    float* p_WtLin  = sym(g_WtLin);
    float* p_WtLin1 = sym(g_WtLin1);
    float* p_WtR1   = sym(g_WtR1);

    cudaFuncSetAttribute(k_hgemm, cudaFuncAttributeMaxDynamicSharedMemorySize, HG_SMEM);

    // graph setup
    k_zero<<<NV / 256, 256>>>();
    k_hist<<<NE / 256, 256>>>(ei);
    k_scan<<<1, 1024>>>();
    k_scatter<<<NE / 256, 256>>>(ei);
    k_degstat<<<NV / 256, 256>>>();
    k_ampatt<<<NV / 256, 256>>>();

    // weight transposes (once)
    dim3 tb(32, 8);
    k_transpose<<<dim3(4, 4), tb>>>(lin1_w, p_WtLin1, NH);
    k_transpose<<<dim3(4, 4), tb>>>(pre_w, p_WtPreA, NH);
    k_transpose<<<dim3(4, 4), tb>>>(pre_w + NH * NH, p_WtPreB, NH);
    k_transpose<<<dim3(KPOST / 32, 4), tb>>>(post_w, p_WtPost, KPOST);
    k_transpose<<<dim3(4, 4), tb>>>(lin_w, p_WtLin, NH);
    k_transpose<<<dim3(4, 4), tb>>>(r1_w, p_WtR1, NH);

    // layer 1 (2 -> 128)
    k_pre1<<<NV / 256, 256>>>(x, pre1_w, pre1_b);
    k_agg1<<<NV / 256, 256>>>(x);
    k_post1<<<NV, 128>>>(post1_w, post1_b);
    k_hgemm<<<NV / 128, 256, HG_SMEM>>>(p_tmp, p_WtLin1, lin1_b, p_state, NH, 0);

    // 3 propagation layers (128 -> 128)
    for (int p = 0; p < 3; p++) {
        k_hgemm<<<NV / 128, 256, HG_SMEM>>>(p_state, p_WtPreA, pre_b, p_Ap, NH, 0);
        k_hgemm<<<NV / 128, 256, HG_SMEM>>>(p_state, p_WtPreB, p_zero, p_Bp, NH, 0);
        k_agg<<<NV, 128>>>();
        k_hgemm<<<NV / 128, 256, HG_SMEM>>>(p_feat, p_WtPost, post_b, p_tmp, KPOST, 0);
        k_hgemm<<<NV / 128, 256, HG_SMEM>>>(p_tmp, p_WtLin, lin_b, p_state, NH, 0);
    }

    // readout
    k_hgemm<<<NV / 128, 256, HG_SMEM>>>(p_state, p_WtR1, r1_b, p_h1, NH, 1);
    k_readout<<<NV / 8, 256>>>(r2_w, r2_b, r3_w, r3_b, tgt_n, out);
    k_loss<<<1, 128>>>(out);

    (void)in_sizes; (void)n_in; (void)out_size;
}

// round 4
// speedup vs baseline: 1.8741x; 1.1494x over previous
#include <cuda_runtime.h>
#include <cuda_bf16.h>
#include <math.h>
#include <stdint.h>

#define NV 32768
#define NE 524288
#define NH 128
#define NB 128
#define NPG 256
#define KF 640            // compressed feature cols: state(128) + mean/std/max/min(512)

typedef unsigned short u16;

// ---------------- helpers ----------------
__device__ __forceinline__ uint32_t smem_u32(const void* p) {
    uint32_t a;
    asm("{ .reg .u64 t; cvta.to.shared.u64 t, %1; cvt.u32.u64 %0, t; }" : "=r"(a) : "l"(p));
    return a;
}

#define LDM_X4(r0, r1, r2, r3, addr)                                         \
    asm volatile("ldmatrix.sync.aligned.m8n8.x4.shared.b16 {%0,%1,%2,%3}, [%4];" \
        : "=r"(r0), "=r"(r1), "=r"(r2), "=r"(r3) : "r"(addr))

#define MMA16816(d, a, b0, b1)                                               \
    asm volatile("mma.sync.aligned.m16n8k16.row.col.f32.bf16.bf16.f32 "      \
        "{%0,%1,%2,%3}, {%4,%5,%6,%7}, {%8,%9}, {%0,%1,%2,%3};"              \
        : "+f"((d)[0]), "+f"((d)[1]), "+f"((d)[2]), "+f"((d)[3])             \
        : "r"((a)[0]), "r"((a)[1]), "r"((a)[2]), "r"((a)[3]),                \
          "r"(b0), "r"(b1))

#define STS128(a, r0, r1, r2, r3)                                            \
    asm volatile("st.shared.v4.b32 [%0], {%1, %2, %3, %4};"                  \
        :: "r"(a), "r"(r0), "r"(r1), "r"(r2), "r"(r3) : "memory")

#define CP16(dst, src)                                                       \
    asm volatile("{ .reg .u64 g; cvta.to.global.u64 g, %1; "                 \
        "cp.async.ca.shared.global [%0], [g], 16; }"                         \
        :: "r"(dst), "l"(src) : "memory")
#define CP_COMMIT() asm volatile("cp.async.commit_group;" ::: "memory")
#define CP_WAIT1()  asm volatile("cp.async.wait_group 1;" ::: "memory")
#define CP_WAIT0()  asm volatile("cp.async.wait_group 0;" ::: "memory")

__device__ __forceinline__ void cvt2(float a, float b, uint32_t& hi, uint32_t& lo) {
    __nv_bfloat16 ha = __float2bfloat16_rn(a), hb = __float2bfloat16_rn(b);
    float ra = a - __bfloat162float(ha);
    float rb = b - __bfloat162float(hb);
    __nv_bfloat16 la = __float2bfloat16_rn(ra), lb = __float2bfloat16_rn(rb);
    u16 uha = *(u16*)&ha, uhb = *(u16*)&hb;
    u16 ula = *(u16*)&la, ulb = *(u16*)&lb;
    hi = ((uint32_t)uhb << 16) | uha;
    lo = ((uint32_t)ulb << 16) | ula;
}

__device__ __forceinline__ void wsplit(u16* ph, u16* pl, float v) {
    __nv_bfloat16 h = __float2bfloat16_rn(v);
    float r = v - __bfloat162float(h);
    __nv_bfloat16 l = __float2bfloat16_rn(r);
    *ph = *(u16*)&h; *pl = *(u16*)&l;
}

// ---------------- scratch ----------------
__device__ int   g_cnt[NV];
__device__ int   g_off[NV + 1];
__device__ int   g_cur[NV];
__device__ int   g_csr[NE];
__device__ float g_logd[NV];
__device__ float g_amp[NV];
__device__ float g_att[NV];
__device__ float g_avg;
__device__ float g_lossb[NB];
__device__ float g_zero128[NH];
__device__ float g_Ap[NV * NH];
__device__ float g_Bp[NV * NH];
__device__ float g_c0[NV * NH];
__device__ float g_c1[NV * NH];
__device__ float g_c2[NV * NH];
__device__ float g_h1[NV * NH];
__device__ float g_A1[NV * 2];
__device__ float g_B1[NV * 2];
__device__ float g_feat1[NV * 26];
// split bf16 planes
__device__ __align__(16) u16 g_sh[NV * NH];          // state hi
__device__ __align__(16) u16 g_sl[NV * NH];          // state lo
__device__ __align__(16) u16 g_fh[(size_t)NV * KF];  // feat hi [V,640]
__device__ __align__(16) u16 g_fl[(size_t)NV * KF];  // feat lo
// weight planes (K-major [128, K])
__device__ __align__(16) u16 g_W0h[NH * KF],  g_W0l[NH * KF];    // [Wx;W0] K=640
__device__ __align__(16) u16 g_W1h[NH * 512], g_W1l[NH * 512];
__device__ __align__(16) u16 g_W2h[NH * 512], g_W2l[NH * 512];
__device__ __align__(16) u16 g_WpAh[NH * NH], g_WpAl[NH * NH];   // pre top
__device__ __align__(16) u16 g_WpBh[NH * NH], g_WpBl[NH * NH];   // pre bottom
__device__ __align__(16) u16 g_Wlh[NH * NH],  g_Wll[NH * NH];    // lin
__device__ __align__(16) u16 g_Wl1h[NH * NH], g_Wl1l[NH * NH];   // lin1
__device__ __align__(16) u16 g_Wr1h[NH * NH], g_Wr1l[NH * NH];   // r1

// ---------------- setup kernels ----------------
__global__ void k_zero() {
    int i = blockIdx.x * blockDim.x + threadIdx.x;
    if (i < NV) { g_cnt[i] = 0; g_cur[i] = 0; }
    if (i < NB) g_lossb[i] = 0.f;
    if (i < NH) g_zero128[i] = 0.f;
    if (i == 0) g_avg = 0.f;
}

__global__ void k_hist(const int* __restrict__ ei) {
    int e = blockIdx.x * blockDim.x + threadIdx.x;
    if (e < NE) atomicAdd(&g_cnt[ei[NE + e]], 1);
}

__global__ void k_scan() {
    __shared__ int sums[1024];
    int t = threadIdx.x;
    int base = t * 32;
    int loc[32];
    int s = 0;
#pragma unroll
    for (int i = 0; i < 32; i++) { loc[i] = s; s += g_cnt[base + i]; }
    sums[t] = s;
    __syncthreads();
    for (int d = 1; d < 1024; d <<= 1) {
        int v = (t >= d) ? sums[t - d] : 0;
        __syncthreads();
        sums[t] += v;
        __syncthreads();
    }
    int excl = sums[t] - s;
#pragma unroll
    for (int i = 0; i < 32; i++) g_off[base + i] = excl + loc[i];
    if (t == 1023) g_off[NV] = excl + s;
}

__global__ void k_scatter(const int* __restrict__ ei) {
    int e = blockIdx.x * blockDim.x + threadIdx.x;
    if (e < NE) {
        int d = ei[NE + e];
        int p = g_off[d] + atomicAdd(&g_cur[d], 1);
        g_csr[p] = ei[e];
    }
}

__global__ void k_degstat() {
    int v = blockIdx.x * blockDim.x + threadIdx.x;
    int d = g_cnt[v];
    float degc = fmaxf((float)d, 1.f);
    g_logd[v] = logf(degc + 1.f);
    float l = logf((float)d + 1.f);
#pragma unroll
    for (int s = 16; s; s >>= 1) l += __shfl_xor_sync(0xffffffffu, l, s);
    if ((threadIdx.x & 31) == 0) atomicAdd(&g_avg, l);
}

__global__ void k_ampatt() {
    int v = blockIdx.x * blockDim.x + threadIdx.x;
    float avg = g_avg / (float)NV;
    float logd = g_logd[v];
    g_amp[v] = logd / avg;
    g_att[v] = avg / logd;
}

// ---------------- weight transpose+split: Wt[n*K+k] = W[k*128+n] ----------------
__global__ void k_tsplit(const float* __restrict__ W, u16* __restrict__ Wh,
                         u16* __restrict__ Wl, int K) {
    __shared__ float tile[32][33];
    int kb = blockIdx.x * 32, nb = blockIdx.y * 32;
    int tx = threadIdx.x, ty = threadIdx.y;
    for (int i = ty; i < 32; i += 8)
        tile[i][tx] = W[(kb + i) * NH + nb + tx];
    __syncthreads();
    for (int i = ty; i < 32; i += 8)
        wsplit(&Wh[(nb + i) * K + kb + tx], &Wl[(nb + i) * K + kb + tx], tile[tx][i]);
}

// ---------------- layer 1 (feature dim 2) ----------------
__global__ void k_pre1(const float* __restrict__ x, const float* __restrict__ w,
                       const float* __restrict__ b) {
    int v = blockIdx.x * blockDim.x + threadIdx.x;
    float x0 = x[2 * v], x1 = x[2 * v + 1];
    g_A1[2 * v + 0] = x0 * w[0] + x1 * w[2] + b[0];
    g_A1[2 * v + 1] = x0 * w[1] + x1 * w[3] + b[1];
    g_B1[2 * v + 0] = x0 * w[4] + x1 * w[6];
    g_B1[2 * v + 1] = x0 * w[5] + x1 * w[7];
}

__global__ void k_agg1(const float* __restrict__ x) {
    int v = blockIdx.x * blockDim.x + threadIdx.x;
    if (v >= NV) return;
    int beg = g_off[v], end = g_off[v + 1];
    float a0 = g_A1[2 * v], a1 = g_A1[2 * v + 1];
    float s0 = 0, s1 = 0, q0 = 0, q1 = 0;
    float mx0 = -3.4e38f, mx1 = -3.4e38f, mn0 = 3.4e38f, mn1 = 3.4e38f;
    for (int e = beg; e < end; e++) {
        int s = g_csr[e];
        float h0 = a0 + g_B1[2 * s];
        float h1 = a1 + g_B1[2 * s + 1];
        s0 += h0; s1 += h1; q0 += h0 * h0; q1 += h1 * h1;
        mx0 = fmaxf(mx0, h0); mx1 = fmaxf(mx1, h1);
        mn0 = fminf(mn0, h0); mn1 = fminf(mn1, h1);
    }
    int d = end - beg;
    float degc = d > 0 ? (float)d : 1.f;
    float m0 = s0 / degc, m1 = s1 / degc;
    float sd0 = sqrtf(fmaxf(q0 / degc - m0 * m0, 0.f) + 1e-5f);
    float sd1 = sqrtf(fmaxf(q1 / degc - m1 * m1, 0.f) + 1e-5f);
    if (d == 0) { mx0 = mx1 = mn0 = mn1 = 0.f; }
    float am = g_amp[v], at = g_att[v];
    float* fr = g_feat1 + v * 26;
    fr[0] = x[2 * v]; fr[1] = x[2 * v + 1];
    fr[2] = m0;  fr[3] = m1;  fr[4] = sd0;  fr[5] = sd1;
    fr[6] = mx0; fr[7] = mx1; fr[8] = mn0;  fr[9] = mn1;
    fr[10] = m0 * am;  fr[11] = m1 * am;  fr[12] = sd0 * am; fr[13] = sd1 * am;
    fr[14] = mx0 * am; fr[15] = mx1 * am; fr[16] = mn0 * am; fr[17] = mn1 * am;
    fr[18] = m0 * at;  fr[19] = m1 * at;  fr[20] = sd0 * at; fr[21] = sd1 * at;
    fr[22] = mx0 * at; fr[23] = mx1 * at; fr[24] = mn0 * at; fr[25] = mn1 * at;
}

__global__ void k_post1(const float* __restrict__ w, const float* __restrict__ b) {
    __shared__ float fr[26];
    int v = blockIdx.x;
    int c = threadIdx.x;
    if (c < 26) fr[c] = g_feat1[v * 26 + c];
    __syncthreads();
    float acc = b[c];
#pragma unroll
    for (int k = 0; k < 26; k++) acc += fr[k] * w[k * NH + c];
    g_c0[v * NH + c] = acc;
}

// ---------------- shared GEMM pieces ----------------
// smem chunk layout: per buffer 40960 B: Ah@0, Al@10240, Bh@20480, Bl@30720
// tile: 128 rows x 32 halves, row stride 40 halves (80 B)

__device__ __forceinline__ void mma_chunk(uint32_t bb, int w, int lane,
                                          float acc[8][2][4]) {
    uint32_t sAh = bb, sAl = bb + 10240, sBh = bb + 20480, sBl = bb + 30720;
    int frow = lane & 15, fcol = (lane >> 4) * 8;
    uint32_t a_base = (uint32_t)((w * 16 + frow) * 40 + fcol) * 2;
    uint32_t b_base = (uint32_t)(frow * 40 + fcol) * 2;
#pragma unroll
    for (int kk = 0; kk < 2; kk++) {
        uint32_t ko = kk * 32;
        uint32_t ah[4], al[4];
        LDM_X4(ah[0], ah[1], ah[2], ah[3], sAh + a_base + ko);
        LDM_X4(al[0], al[1], al[2], al[3], sAl + a_base + ko);
#pragma unroll
        for (int g = 0; g < 8; g++) {
            uint32_t go = (uint32_t)(g * 16 * 40) * 2;
            uint32_t bh0, bh1, bh2, bh3, bl0, bl1, bl2, bl3;
            LDM_X4(bh0, bh1, bh2, bh3, sBh + b_base + go + ko);
            LDM_X4(bl0, bl1, bl2, bl3, sBl + b_base + go + ko);
            MMA16816(acc[g][0], ah, bh0, bh2);
            MMA16816(acc[g][0], ah, bl0, bl2);
            MMA16816(acc[g][0], al, bh0, bh2);
            MMA16816(acc[g][1], ah, bh1, bh3);
            MMA16816(acc[g][1], ah, bl1, bl3);
            MMA16816(acc[g][1], al, bh1, bh3);
        }
    }
}

__device__ __forceinline__ void epilogue(float acc[8][2][4], char* dsm,
                                         int w, int lane, int t, int m0,
                                         const float* bias, int act,
                                         float* Cf, u16* Coh, u16* Col) {
    float* stage = (float*)dsm;
#pragma unroll
    for (int rc = 0; rc < 4; rc++) {
        __syncthreads();
        if ((w >> 1) == rc) {
            int r0 = (w & 1) * 16 + (lane >> 2);
            int cb = (lane & 3) * 2;
#pragma unroll
            for (int g = 0; g < 8; g++)
#pragma unroll
                for (int h = 0; h < 2; h++) {
                    int col = g * 16 + h * 8 + cb;
                    stage[r0 * 132 + col] = acc[g][h][0];
                    stage[r0 * 132 + col + 1] = acc[g][h][1];
                    stage[(r0 + 8) * 132 + col] = acc[g][h][2];
                    stage[(r0 + 8) * 132 + col + 1] = acc[g][h][3];
                }
        }
        __syncthreads();
#pragma unroll
        for (int i = 0; i < 4; i++) {
            int idx = t + i * 256;
            int row = idx >> 5;
            int c4 = (idx & 31) * 4;
            float4 v = *(const float4*)(stage + row * 132 + c4);
            v.x += __ldg(&bias[c4 + 0]); v.y += __ldg(&bias[c4 + 1]);
            v.z += __ldg(&bias[c4 + 2]); v.w += __ldg(&bias[c4 + 3]);
            if (act) {
                if (v.x < 0.f) v.x *= 0.01f;
                if (v.y < 0.f) v.y *= 0.01f;
                if (v.z < 0.f) v.z *= 0.01f;
                if (v.w < 0.f) v.w *= 0.01f;
            }
            int grow = m0 + rc * 32 + row;
            if (Coh) {
                uint32_t h0, l0, h1, l1;
                cvt2(v.x, v.y, h0, l0); cvt2(v.z, v.w, h1, l1);
                uint2 hv = {h0, h1}, lv = {l0, l1};
                *(uint2*)(Coh + (size_t)grow * 128 + c4) = hv;
                *(uint2*)(Col + (size_t)grow * 128 + c4) = lv;
            } else {
                *(float4*)(Cf + (size_t)grow * 128 + c4) = v;
            }
        }
    }
}

// ---------------- GEMM, pre-split bf16 A (cp.async pipelined) ----------------
__global__ void __launch_bounds__(256) k_gemm_bf(
    const u16* __restrict__ Ah, const u16* __restrict__ Al, int lda, int K,
    const u16* __restrict__ Bh, const u16* __restrict__ Bl,
    const float* __restrict__ bias, int act,
    float* __restrict__ Cf, u16* __restrict__ Coh, u16* __restrict__ Col) {
    extern __shared__ char dsm[];
    uint32_t sb = smem_u32(dsm);
    int t = threadIdx.x, w = t >> 5, lane = t & 31;
    int m0 = blockIdx.x * 128;
    float acc[8][2][4] = {};
    int row = t >> 1, sseg = (t & 1) * 16;
    const u16* aH = Ah + (size_t)(m0 + row) * lda + sseg;
    const u16* aL = Al + (size_t)(m0 + row) * lda + sseg;
    const u16* bH = Bh + (size_t)row * K + sseg;
    const u16* bL = Bl + (size_t)row * K + sseg;
    uint32_t so = (uint32_t)(row * 40 + sseg) * 2;
    int nch = K >> 5;
    {
        uint32_t bb = sb;
        CP16(bb + so, aH); CP16(bb + so + 16, aH + 8);
        CP16(bb + 10240 + so, aL); CP16(bb + 10240 + so + 16, aL + 8);
        CP16(bb + 20480 + so, bH); CP16(bb + 20480 + so + 16, bH + 8);
        CP16(bb + 30720 + so, bL); CP16(bb + 30720 + so + 16, bL + 8);
        CP_COMMIT();
    }
    for (int ch = 0; ch < nch; ch++) {
        if (ch + 1 < nch) {
            int k0 = (ch + 1) << 5;
            uint32_t bb = sb + ((ch + 1) & 1) * 40960;
            CP16(bb + so, aH + k0); CP16(bb + so + 16, aH + k0 + 8);
            CP16(bb + 10240 + so, aL + k0); CP16(bb + 10240 + so + 16, aL + k0 + 8);
            CP16(bb + 20480 + so, bH + k0); CP16(bb + 20480 + so + 16, bH + k0 + 8);
            CP16(bb + 30720 + so, bL + k0); CP16(bb + 30720 + so + 16, bL + k0 + 8);
            CP_COMMIT();
            CP_WAIT1();
        } else {
            CP_WAIT0();
        }
        __syncthreads();
        mma_chunk(sb + (ch & 1) * 40960, w, lane, acc);
        __syncthreads();
    }
    epilogue(acc, dsm, w, lane, t, m0, bias, act, Cf, Coh, Col);
}

// ---------------- GEMM, fp32 A with optional 3-way combine (K=128) ----------------
__global__ void __launch_bounds__(256) k_gemm_f(
    const float* __restrict__ A0, const float* __restrict__ A1,
    const float* __restrict__ A2, const float* __restrict__ amp,
    const float* __restrict__ att, int ncomb,
    const u16* __restrict__ Bh, const u16* __restrict__ Bl,
    const float* __restrict__ bias, int act,
    float* __restrict__ Cf, u16* __restrict__ Coh, u16* __restrict__ Col) {
    extern __shared__ char dsm[];
    uint32_t sb = smem_u32(dsm);
    int t = threadIdx.x, w = t >> 5, lane = t & 31;
    int m0 = blockIdx.x * 128;
    float acc[8][2][4] = {};
    int row = t >> 1, sseg = (t & 1) * 16;
    int grow = m0 + row;
    float sc1 = 0.f, sc2 = 0.f;
    if (ncomb == 3) { sc1 = amp[grow]; sc2 = att[grow]; }
    const float* a0 = A0 + (size_t)grow * 128 + sseg;
    const float* a1 = (ncomb == 3) ? A1 + (size_t)grow * 128 + sseg : a0;
    const float* a2 = (ncomb == 3) ? A2 + (size_t)grow * 128 + sseg : a0;
    const u16* bH = Bh + (size_t)row * 128 + sseg;
    const u16* bL = Bl + (size_t)row * 128 + sseg;
    uint32_t so = (uint32_t)(row * 40 + sseg) * 2;
    for (int ch = 0; ch < 4; ch++) {
        int k0 = ch << 5;
        // A: 16 floats, combined, split
        float av[16];
#pragma unroll
        for (int q = 0; q < 4; q++) {
            float4 v0 = *(const float4*)(a0 + k0 + q * 4);
            av[q * 4 + 0] = v0.x; av[q * 4 + 1] = v0.y;
            av[q * 4 + 2] = v0.z; av[q * 4 + 3] = v0.w;
        }
        if (ncomb == 3) {
#pragma unroll
            for (int q = 0; q < 4; q++) {
                float4 v1 = *(const float4*)(a1 + k0 + q * 4);
                float4 v2 = *(const float4*)(a2 + k0 + q * 4);
                av[q * 4 + 0] += sc1 * v1.x + sc2 * v2.x;
                av[q * 4 + 1] += sc1 * v1.y + sc2 * v2.y;
                av[q * 4 + 2] += sc1 * v1.z + sc2 * v2.z;
                av[q * 4 + 3] += sc1 * v1.w + sc2 * v2.w;
            }
        }
        uint32_t hi[8], lo[8];
#pragma unroll
        for (int q = 0; q < 8; q++) cvt2(av[2 * q], av[2 * q + 1], hi[q], lo[q]);
        STS128(sb + so, hi[0], hi[1], hi[2], hi[3]);
        STS128(sb + so + 16, hi[4], hi[5], hi[6], hi[7]);
        STS128(sb + 10240 + so, lo[0], lo[1], lo[2], lo[3]);
        STS128(sb + 10240 + so + 16, lo[4], lo[5], lo[6], lo[7]);
        // B: direct vector copy of presplit planes
        uint4 vh0 = *(const uint4*)(bH + k0);
        uint4 vh1 = *(const uint4*)(bH + k0 + 8);
        uint4 vl0 = *(const uint4*)(bL + k0);
        uint4 vl1 = *(const uint4*)(bL + k0 + 8);
        STS128(sb + 20480 + so, vh0.x, vh0.y, vh0.z, vh0.w);
        STS128(sb + 20480 + so + 16, vh1.x, vh1.y, vh1.z, vh1.w);
        STS128(sb + 30720 + so, vl0.x, vl0.y, vl0.z, vl0.w);
        STS128(sb + 30720 + so + 16, vl1.x, vl1.y, vl1.z, vl1.w);
        __syncthreads();
        mma_chunk(sb, w, lane, acc);
        __syncthreads();
    }
    epilogue(acc, dsm, w, lane, t, m0, bias, act, Cf, Coh, Col);
}

// ---------------- aggregation: writes split-bf16 feat [V,640] ----------------
__global__ void __launch_bounds__(128) k_agg() {
    __shared__ int s_src[128];
    int v = blockIdx.x;
    int f = threadIdx.x;
    int beg = g_off[v], end = g_off[v + 1];
    float a = g_Ap[v * NH + f];
    float sum = 0.f, sq = 0.f, mx = -3.4e38f, mn = 3.4e38f;
    for (int base = beg; base < end; base += 128) {
        int n = min(128, end - base);
        if (f < n) s_src[f] = g_csr[base + f];
        __syncthreads();
        int e = 0;
        for (; e + 4 <= n; e += 4) {
            int i0 = s_src[e], i1 = s_src[e + 1], i2 = s_src[e + 2], i3 = s_src[e + 3];
            float h0 = a + g_Bp[i0 * NH + f];
            float h1 = a + g_Bp[i1 * NH + f];
            float h2 = a + g_Bp[i2 * NH + f];
            float h3 = a + g_Bp[i3 * NH + f];
            sum += h0 + h1 + h2 + h3;
            sq += h0 * h0 + h1 * h1 + h2 * h2 + h3 * h3;
            mx = fmaxf(mx, fmaxf(fmaxf(h0, h1), fmaxf(h2, h3)));
            mn = fminf(mn, fminf(fminf(h0, h1), fminf(h2, h3)));
        }
        for (; e < n; e++) {
            float h = a + g_Bp[s_src[e] * NH + f];
            sum += h; sq += h * h; mx = fmaxf(mx, h); mn = fminf(mn, h);
        }
        __syncthreads();
    }
    int d = end - beg;
    float degc = d > 0 ? (float)d : 1.f;
    float mean = sum / degc;
    float stdv = sqrtf(fmaxf(sq / degc - mean * mean, 0.f) + 1e-5f);
    if (d == 0) { mx = 0.f; mn = 0.f; }
    size_t fb = (size_t)v * KF;
    g_fh[fb + f] = g_sh[v * NH + f];
    g_fl[fb + f] = g_sl[v * NH + f];
    wsplit(&g_fh[fb + 128 + f], &g_fl[fb + 128 + f], mean);
    wsplit(&g_fh[fb + 256 + f], &g_fl[fb + 256 + f], stdv);
    wsplit(&g_fh[fb + 384 + f], &g_fl[fb + 384 + f], mx);
    wsplit(&g_fh[fb + 512 + f], &g_fl[fb + 512 + f], mn);
}

// ---------------- readout tail ----------------
__global__ void __launch_bounds__(256) k_readout(const float* __restrict__ r2w,
                                                 const float* __restrict__ r2b,
                                                 const float* __restrict__ r3w,
                                                 const float* __restrict__ r3b,
                                                 const float* __restrict__ tgt,
                                                 float* __restrict__ out) {
    __shared__ float w2[128 * 8];
    int t = threadIdx.x;
    for (int i = t; i < 128 * 8; i += 256) w2[i] = r2w[i];
    __syncthreads();
    int warp = t >> 5, lane = t & 31;
    int v = blockIdx.x * 8 + warp;
    const float* h1 = g_h1 + v * NH;
    float p[8] = {0, 0, 0, 0, 0, 0, 0, 0};
    for (int k = lane; k < 128; k += 32) {
        float hv = h1[k];
#pragma unroll
        for (int j = 0; j < 8; j++) p[j] += hv * w2[k * 8 + j];
    }
#pragma unroll
    for (int j = 0; j < 8; j++)
#pragma unroll
        for (int s = 16; s; s >>= 1) p[j] += __shfl_xor_sync(0xffffffffu, p[j], s);
    if (lane == 0) {
        float h2[8];
#pragma unroll
        for (int j = 0; j < 8; j++) {
            float x = p[j] + r2b[j];
            h2[j] = x < 0.f ? 0.01f * x : x;
        }
        float err = 0.f;
#pragma unroll
        for (int c = 0; c < 3; c++) {
            float o = r3b[c];
#pragma unroll
            for (int j = 0; j < 8; j++) o += h2[j] * r3w[j * 3 + c];
            if (o < 0.f) o *= 0.01f;
            out[v * 3 + c] = o;
            float dd = o - tgt[v * 3 + c];
            err += dd * dd;
        }
        atomicAdd(&g_lossb[v >> 8], err);
    }
}

__global__ void k_loss(float* __restrict__ out) {
    __shared__ float s[128];
    int b = threadIdx.x;
    float l = g_lossb[b] / (float)(NPG * 3);
    out[NV * 3 + 1 + b] = l;
    s[b] = l;
    __syncthreads();
    for (int d = 64; d; d >>= 1) {
        if (b < d) s[b] += s[b + d];
        __syncthreads();
    }
    if (b == 0) out[NV * 3] = s[0] / (float)NB;
}

// ---------------- host ----------------
template <typename T>
static void* symv(T& s) { void* p = nullptr; cudaGetSymbolAddress(&p, s); return p; }

extern "C" void kernel_launch(void* const* d_in, const int* in_sizes, int n_in,
                              void* d_out, int out_size) {
    const float* x       = (const float*)d_in[0];
    const int*   ei      = (const int*)d_in[1];
    const float* tgt_n   = (const float*)d_in[2];
    const float* pre1_w  = (const float*)d_in[4];
    const float* pre1_b  = (const float*)d_in[5];
    const float* post1_w = (const float*)d_in[6];
    const float* post1_b = (const float*)d_in[7];
    const float* lin1_w  = (const float*)d_in[8];
    const float* lin1_b  = (const float*)d_in[9];
    const float* pre_w   = (const float*)d_in[10];
    const float* pre_b   = (const float*)d_in[11];
    const float* post_w  = (const float*)d_in[12];
    const float* post_b  = (const float*)d_in[13];
    const float* lin_w   = (const float*)d_in[14];
    const float* lin_b   = (const float*)d_in[15];
    const float* r1_w    = (const float*)d_in[16];
    const float* r1_b    = (const float*)d_in[17];
    const float* r2_w    = (const float*)d_in[18];
    const float* r2_b    = (const float*)d_in[19];
    const float* r3_w    = (const float*)d_in[20];
    const float* r3_b    = (const float*)d_in[21];
    float* out = (float*)d_out;

    float* p_Ap  = (float*)symv(g_Ap);
    float* p_Bp  = (float*)symv(g_Bp);
    float* p_c0  = (float*)symv(g_c0);
    float* p_c1  = (float*)symv(g_c1);
    float* p_c2  = (float*)symv(g_c2);
    float* p_h1  = (float*)symv(g_h1);
    float* p_amp = (float*)symv(g_amp);
    float* p_att = (float*)symv(g_att);
    float* p_z   = (float*)symv(g_zero128);
    u16* p_sh  = (u16*)symv(g_sh);
    u16* p_sl  = (u16*)symv(g_sl);
    u16* p_fh  = (u16*)symv(g_fh);
    u16* p_fl  = (u16*)symv(g_fl);
    u16* p_W0h = (u16*)symv(g_W0h);  u16* p_W0l = (u16*)symv(g_W0l);
    u16* p_W1h = (u16*)symv(g_W1h);  u16* p_W1l = (u16*)symv(g_W1l);
    u16* p_W2h = (u16*)symv(g_W2h);  u16* p_W2l = (u16*)symv(g_W2l);
    u16* p_WpAh = (u16*)symv(g_WpAh); u16* p_WpAl = (u16*)symv(g_WpAl);
    u16* p_WpBh = (u16*)symv(g_WpBh); u16* p_WpBl = (u16*)symv(g_WpBl);
    u16* p_Wlh = (u16*)symv(g_Wlh);   u16* p_Wll = (u16*)symv(g_Wll);
    u16* p_Wl1h = (u16*)symv(g_Wl1h); u16* p_Wl1l = (u16*)symv(g_Wl1l);
    u16* p_Wr1h = (u16*)symv(g_Wr1h); u16* p_Wr1l = (u16*)symv(g_Wr1l);

    cudaFuncSetAttribute(k_gemm_bf, cudaFuncAttributeMaxDynamicSharedMemorySize, 81920);
    cudaFuncSetAttribute(k_gemm_f, cudaFuncAttributeMaxDynamicSharedMemorySize, 40960);

    // graph setup
    k_zero<<<NV / 256, 256>>>();
    k_hist<<<NE / 256, 256>>>(ei);
    k_scan<<<1, 1024>>>();
    k_scatter<<<NE / 256, 256>>>(ei);
    k_degstat<<<NV / 256, 256>>>();
    k_ampatt<<<NV / 256, 256>>>();

    // weight transposes + splits (once per launch)
    dim3 tb(32, 8);
    k_tsplit<<<dim3(4, 4), tb>>>(lin1_w, p_Wl1h, p_Wl1l, NH);
    k_tsplit<<<dim3(4, 4), tb>>>(pre_w, p_WpAh, p_WpAl, NH);
    k_tsplit<<<dim3(4, 4), tb>>>(pre_w + NH * NH, p_WpBh, p_WpBl, NH);
    k_tsplit<<<dim3(KF / 32, 4), tb>>>(post_w, p_W0h, p_W0l, KF);
    k_tsplit<<<dim3(16, 4), tb>>>(post_w + 640 * NH, p_W1h, p_W1l, 512);
    k_tsplit<<<dim3(16, 4), tb>>>(post_w + 1152 * NH, p_W2h, p_W2l, 512);
    k_tsplit<<<dim3(4, 4), tb>>>(lin_w, p_Wlh, p_Wll, NH);
    k_tsplit<<<dim3(4, 4), tb>>>(r1_w, p_Wr1h, p_Wr1l, NH);

    // layer 1 (2 -> 128)
    k_pre1<<<NV / 256, 256>>>(x, pre1_w, pre1_b);
    k_agg1<<<NV / 256, 256>>>(x);
    k_post1<<<NV, 128>>>(post1_w, post1_b);
    k_gemm_f<<<NV / 128, 256, 40960>>>(p_c0, 0, 0, 0, 0, 1, p_Wl1h, p_Wl1l,
                                       lin1_b, 0, 0, p_sh, p_sl);

    // 3 propagation layers (128 -> 128)
    for (int p = 0; p < 3; p++) {
        k_gemm_bf<<<NV / 128, 256, 81920>>>(p_sh, p_sl, NH, NH, p_WpAh, p_WpAl,
                                            pre_b, 0, p_Ap, 0, 0);
        k_gemm_bf<<<NV / 128, 256, 81920>>>(p_sh, p_sl, NH, NH, p_WpBh, p_WpBl,
                                            p_z, 0, p_Bp, 0, 0);
        k_agg<<<NV, 128>>>();
        k_gemm_bf<<<NV / 128, 256, 81920>>>(p_fh, p_fl, KF, KF, p_W0h, p_W0l,
                                            post_b, 0, p_c0, 0, 0);
        k_gemm_bf<<<NV / 128, 256, 81920>>>(p_fh + 128, p_fl + 128, KF, 512,
                                            p_W1h, p_W1l, p_z, 0, p_c1, 0, 0);
        k_gemm_bf<<<NV / 128, 256, 81920>>>(p_fh + 128, p_fl + 128, KF, 512,
                                            p_W2h, p_W2l, p_z, 0, p_c2, 0, 0);
        k_gemm_f<<<NV / 128, 256, 40960>>>(p_c0, p_c1, p_c2, p_amp, p_att, 3,
                                           p_Wlh, p_Wll, lin_b, 0, 0, p_sh, p_sl);
    }

    // readout
    k_gemm_bf<<<NV / 128, 256, 81920>>>(p_sh, p_sl, NH, NH, p_Wr1h, p_Wr1l,
                                        r1_b, 1, p_h1, 0, 0);
    k_readout<<<NV / 8, 256>>>(r2_w, r2_b, r3_w, r3_b, tgt_n, out);
    k_loss<<<1, 128>>>(out);

    (void)in_sizes; (void)n_in; (void)out_size;
}